// round 13
// baseline (speedup 1.0000x reference)
#include <cuda_runtime.h>
#include <cuda_fp16.h>
#include <cstdint>

#define NN 100000
#define EE 1600000
#define HH 128
#define LL 3
#define GG 512
#define LAT 64
#define SLOPE 0.2f
#define BN_EPS 1e-5f
#define NB_SCAN 98   // ceil(NN/1024)

// ---------------- device scratch (all activations fp16) ----------------
__device__ uint2 g_x16[NN * 32];   // fp16 x
__device__ uint2 g_h16[NN * 32];   // fp16 h
__device__ uint2 g_s16[NN * 32];   // fp16 s = h + agg
__device__ int   g_deg[NN];        // INVARIANT: zero at launch entry (re-zeroed in k_scan)
__device__ int   g_rs[NN + 1];
__device__ int   g_cur[NN];
__device__ int   g_col[EE];
__device__ int   g_bsum[128];      // INVARIANT: zero at launch entry (re-zeroed in k_scatter)
__device__ int   g_gst[GG + 1];
__device__ float g_a1[LL * HH];
__device__ float g_c1[LL * HH];
__device__ float g_ap[HH];
__device__ float g_cp[HH];
__device__ uint2 g_wb[6 * 4096];   // fp16 fragment-packed weights, 32KB/matrix

// ---------------- helpers ----------------
__device__ __forceinline__ uint32_t packh2(float a, float b) {
    __half2 h = __float22half2_rn(make_float2(a, b));
    return *(uint32_t*)&h;
}

__device__ __forceinline__ void mma_f16(float* d, const uint4& a, const uint2& b) {
    asm volatile(
        "mma.sync.aligned.m16n8k16.row.col.f32.f16.f16.f32 "
        "{%0,%1,%2,%3},{%4,%5,%6,%7},{%8,%9},{%0,%1,%2,%3};"
        : "+f"(d[0]), "+f"(d[1]), "+f"(d[2]), "+f"(d[3])
        : "r"(a.x), "r"(a.y), "r"(a.z), "r"(a.w), "r"(b.x), "r"(b.y));
}

// ---------------- merged setup + degree histogram ----------------
__global__ void __launch_bounds__(256) k_setup(
    const float* __restrict__ x, const int* __restrict__ batch,
    const int* __restrict__ dst,
    const float* __restrict__ g1, const float* __restrict__ beta1,
    const float* __restrict__ rm1, const float* __restrict__ rv1,
    const float* __restrict__ bng, const float* __restrict__ bnb,
    const float* __restrict__ bnrm, const float* __restrict__ bnrv,
    const float* __restrict__ W1, const float* __restrict__ W2) {
    int b = blockIdx.x, tid = threadIdx.x;
    if (b < 3200) {
        const float4* x4 = (const float4*)x;
#pragma unroll
        for (int i = 0; i < 4; i++) {
            int idx = (b * 256 + tid) * 4 + i;
            if (idx < NN * 32) {
                float4 v = x4[idx];
                g_x16[idx] = make_uint2(packh2(v.x, v.y), packh2(v.z, v.w));
            }
        }
    } else if (b < 9450) {
        int e = (b - 3200) * 256 + tid;
        if (e < EE) atomicAdd(&g_deg[dst[e]], 1);
    } else if (b < 9452) {
        int t = (b - 9450) * 256 + tid;   // 0..511
        if (t < LL * HH) {
            float a = g1[t] * rsqrtf(rv1[t] + BN_EPS);
            g_a1[t] = a;
            g_c1[t] = beta1[t] - a * rm1[t];
        }
        if (t < HH) {
            float a = bng[t] * rsqrtf(bnrv[t] + BN_EPS);
            g_ap[t] = a;
            g_cp[t] = bnb[t] - a * bnrm[t];
        }
        int lo = 0, hi = NN;
        while (lo < hi) { int m = (lo + hi) >> 1; if (batch[m] < t) lo = m + 1; else hi = m; }
        g_gst[t] = lo;
        if (t == 0) g_gst[GG] = NN;
    } else {
        int mat = b - 9452;   // 0..5
        int l = mat >> 1, ph = mat & 1;
        const float* w = (ph ? W2 : W1) + l * HH * HH;
        uint2* outp = &g_wb[mat * 4096];
#pragma unroll
        for (int i = 0; i < 16; i++) {
            int s = tid + i * 256;
            int nt = s >> 8, ks = (s >> 5) & 7, lane = s & 31;
            int k0 = ks * 16 + (lane & 3) * 2;
            int n = nt * 8 + (lane >> 2);
            outp[s] = make_uint2(packh2(w[k0 * HH + n], w[(k0 + 1) * HH + n]),
                                 packh2(w[(k0 + 8) * HH + n], w[(k0 + 9) * HH + n]));
        }
    }
}

// ---------------- single-pass scan (decoupled lookback, 98 resident blocks) --------
__global__ void __launch_bounds__(1024) k_scan() {
    __shared__ int sm[1024];
    __shared__ int carry;
    int t = threadIdx.x, b = blockIdx.x;
    int i = b * 1024 + t;
    int v = (i < NN) ? g_deg[i] : 0;
    sm[t] = v;
    if (t == 0) carry = 0;
    __syncthreads();
    for (int off = 1; off < 1024; off <<= 1) {
        int u = (t >= off) ? sm[t - off] : 0;
        __syncthreads();
        sm[t] += u;
        __syncthreads();
    }
    int incl = sm[t];
    if (t == 1023) atomicExch(&g_bsum[b], sm[1023] + 1);   // publish aggregate+1
    if (t < b) {
        int f;
        do { f = atomicAdd(&g_bsum[t], 0); } while (f == 0);
        atomicAdd(&carry, f - 1);
    }
    __syncthreads();
    int off0 = carry;
    if (i < NN) {
        int inc2 = incl + off0;
        g_rs[i + 1] = inc2;
        g_cur[i] = inc2 - v;
        g_deg[i] = 0;          // restore invariant for next launch
    }
    if (i == 0) g_rs[0] = 0;
}

__global__ void k_scatter(const int* __restrict__ src, const int* __restrict__ dst) {
    if (blockIdx.x < NB_SCAN && threadIdx.x == 0) g_bsum[blockIdx.x] = 0;  // invariant
    int e = blockIdx.x * blockDim.x + threadIdx.x;
    if (e < EE) {
        int p = atomicAdd(&g_cur[dst[e]], 1);
        g_col[p] = src[e];
    }
}

// ---------------- aggregation: warp per node, half-warp x uint4, 2 neighbors/instr --
__global__ void __launch_bounds__(256) k_agg(int layer) {
    const uint4* __restrict__ H4 = (const uint4*)((layer == 0) ? g_x16 : g_h16);
    int w = threadIdx.x >> 5, lane = threadIdx.x & 31;
    int node = blockIdx.x * 8 + w;
    if (node >= NN) return;
    int half = lane >> 4;      // 0: even neighbors, 1: odd neighbors
    int hl = lane & 15;        // covers cols 8*hl .. 8*hl+7
    int beg = g_rs[node], end = g_rs[node + 1];
    float a0 = 0.f, a1 = 0.f, a2 = 0.f, a3 = 0.f,
          a4 = 0.f, a5 = 0.f, a6 = 0.f, a7 = 0.f;
    if (half == 0) {   // self term, half 0 only (halves are summed at the end)
        uint4 sv = H4[node * 16 + hl];
        float2 f;
        f = __half22float2(*(__half2*)&sv.x); a0 = f.x; a1 = f.y;
        f = __half22float2(*(__half2*)&sv.y); a2 = f.x; a3 = f.y;
        f = __half22float2(*(__half2*)&sv.z); a4 = f.x; a5 = f.y;
        f = __half22float2(*(__half2*)&sv.w); a6 = f.x; a7 = f.y;
    }
    const __half2 hz = __float2half2_rn(0.f);
    for (int j = beg; j < end; j += 32) {
        int cnt = min(32, end - j);
        int idx = (lane < cnt) ? g_col[j + lane] : 0;
        int pairs = cnt >> 1;
        int u = 0;
        for (; u + 4 <= pairs; u += 4) {          // 8 neighbors; 4 fp16 adds per slot
            __half2 c0 = hz, c1 = hz, c2 = hz, c3 = hz;
#pragma unroll
            for (int p = 0; p < 4; p++) {
                int jj = __shfl_sync(0xffffffffu, idx, 2 * (u + p) + half);
                uint4 v = H4[jj * 16 + hl];
                c0 = __hadd2(c0, *(__half2*)&v.x);
                c1 = __hadd2(c1, *(__half2*)&v.y);
                c2 = __hadd2(c2, *(__half2*)&v.z);
                c3 = __hadd2(c3, *(__half2*)&v.w);
            }
            float2 f;
            f = __half22float2(c0); a0 += f.x; a1 += f.y;
            f = __half22float2(c1); a2 += f.x; a3 += f.y;
            f = __half22float2(c2); a4 += f.x; a5 += f.y;
            f = __half22float2(c3); a6 += f.x; a7 += f.y;
        }
        for (; u < pairs; u++) {
            int jj = __shfl_sync(0xffffffffu, idx, 2 * u + half);
            uint4 v = H4[jj * 16 + hl];
            float2 f;
            f = __half22float2(*(__half2*)&v.x); a0 += f.x; a1 += f.y;
            f = __half22float2(*(__half2*)&v.y); a2 += f.x; a3 += f.y;
            f = __half22float2(*(__half2*)&v.z); a4 += f.x; a5 += f.y;
            f = __half22float2(*(__half2*)&v.w); a6 += f.x; a7 += f.y;
        }
        if (cnt & 1) {         // odd tail neighbor: half 0 handles it
            int jj = __shfl_sync(0xffffffffu, idx, cnt - 1);
            if (half == 0) {
                uint4 v = H4[jj * 16 + hl];
                float2 f;
                f = __half22float2(*(__half2*)&v.x); a0 += f.x; a1 += f.y;
                f = __half22float2(*(__half2*)&v.y); a2 += f.x; a3 += f.y;
                f = __half22float2(*(__half2*)&v.z); a4 += f.x; a5 += f.y;
                f = __half22float2(*(__half2*)&v.w); a6 += f.x; a7 += f.y;
            }
        }
    }
    // combine even/odd half-sums
    a0 += __shfl_xor_sync(0xffffffffu, a0, 16);
    a1 += __shfl_xor_sync(0xffffffffu, a1, 16);
    a2 += __shfl_xor_sync(0xffffffffu, a2, 16);
    a3 += __shfl_xor_sync(0xffffffffu, a3, 16);
    a4 += __shfl_xor_sync(0xffffffffu, a4, 16);
    a5 += __shfl_xor_sync(0xffffffffu, a5, 16);
    a6 += __shfl_xor_sync(0xffffffffu, a6, 16);
    a7 += __shfl_xor_sync(0xffffffffu, a7, 16);
    if (half == 0) {
        uint4 o;
        o.x = packh2(a0, a1);
        o.y = packh2(a2, a3);
        o.z = packh2(a4, a5);
        o.w = packh2(a6, a7);
        ((uint4*)g_s16)[node * 16 + hl] = o;
    }
}

// ---------------- fused MLP, fp16 single-term HMMA (round-5 proven) -----------------
__global__ void __launch_bounds__(256, 2) k_mlp(const float* __restrict__ b1,
                                                const float* __restrict__ b2, int l) {
    extern __shared__ char sm[];
    uint4* As = (uint4*)sm;
    uint2* Bs1 = (uint2*)(sm + 32768);
    uint2* Bs2 = (uint2*)(sm + 65536);

    int tid = threadIdx.x, wid = tid >> 5, lane = tid & 31;
    int warp_m = wid >> 2, warp_n = wid & 3;
    int m0 = blockIdx.x * 128;

    {
        const uint4* src = (const uint4*)&g_wb[l * 8192];
        uint4* dst = (uint4*)Bs1;
#pragma unroll
        for (int i = 0; i < 16; i++) dst[tid + i * 256] = src[tid + i * 256];
    }

    const uint32_t* __restrict__ S32 = (const uint32_t*)g_s16;
#pragma unroll
    for (int i = 0; i < 8; i++) {
        int s = tid + i * 256;
        int mt = s >> 8, ks = (s >> 5) & 7, ln = s & 31;
        int r = m0 + mt * 16 + (ln >> 2);
        int cp = ks * 8 + (ln & 3);
        uint4 a = make_uint4(0u, 0u, 0u, 0u);
        if (r < NN)     { a.x = S32[r * 64 + cp];       a.z = S32[r * 64 + cp + 4]; }
        if (r + 8 < NN) { a.y = S32[(r + 8) * 64 + cp]; a.w = S32[(r + 8) * 64 + cp + 4]; }
        As[s] = a;
    }
    __syncthreads();

    float d[4][4][4];
#pragma unroll
    for (int mt = 0; mt < 4; mt++)
#pragma unroll
        for (int nt = 0; nt < 4; nt++)
#pragma unroll
            for (int q = 0; q < 4; q++) d[mt][nt][q] = 0.f;

    // ---- GEMM1 ----
#pragma unroll 1
    for (int ks = 0; ks < 8; ks++) {
        uint4 ah[4];
#pragma unroll
        for (int mt = 0; mt < 4; mt++)
            ah[mt] = As[((warp_m * 4 + mt) * 8 + ks) * 32 + lane];
#pragma unroll
        for (int nt = 0; nt < 4; nt++) {
            uint2 bh = Bs1[((warp_n * 4 + nt) * 8 + ks) * 32 + lane];
#pragma unroll
            for (int mt = 0; mt < 4; mt++) mma_f16(d[mt][nt], ah[mt], bh);
        }
    }

    // ---- epilogue1 -> GEMM2 A-fragments (in-register) ----
    uint4 tf[4][2];
    {
        float aa[8], cc[8], bb[8];
#pragma unroll
        for (int j = 0; j < 8; j++) {
            int c = warp_n * 32 + (j >> 1) * 8 + (lane & 3) * 2 + (j & 1);
            bb[j] = b1[c];
            aa[j] = g_a1[l * HH + c];
            cc[j] = g_c1[l * HH + c];
        }
#pragma unroll
        for (int mt = 0; mt < 4; mt++) {
#pragma unroll
            for (int nt = 0; nt < 4; nt++) {
#pragma unroll
                for (int q = 0; q < 4; q++) {
                    float v = d[mt][nt][q] + bb[nt * 2 + (q & 1)];
                    v = v > 0.f ? v : SLOPE * v;
                    d[mt][nt][q] = aa[nt * 2 + (q & 1)] * v + cc[nt * 2 + (q & 1)];
                }
            }
#pragma unroll
            for (int kp = 0; kp < 2; kp++) {
                tf[mt][kp].x = packh2(d[mt][2 * kp][0],     d[mt][2 * kp][1]);
                tf[mt][kp].y = packh2(d[mt][2 * kp][2],     d[mt][2 * kp][3]);
                tf[mt][kp].z = packh2(d[mt][2 * kp + 1][0], d[mt][2 * kp + 1][1]);
                tf[mt][kp].w = packh2(d[mt][2 * kp + 1][2], d[mt][2 * kp + 1][3]);
            }
        }
    }
    __syncthreads();
#pragma unroll
    for (int mt = 0; mt < 4; mt++)
#pragma unroll
        for (int kp = 0; kp < 2; kp++)
            As[((warp_m * 4 + mt) * 8 + warp_n * 2 + kp) * 32 + lane] = tf[mt][kp];
    __syncthreads();

#pragma unroll
    for (int mt = 0; mt < 4; mt++)
#pragma unroll
        for (int nt = 0; nt < 4; nt++)
#pragma unroll
            for (int q = 0; q < 4; q++) d[mt][nt][q] = 0.f;

    // ---- GEMM2 ----
#pragma unroll 1
    for (int ks = 0; ks < 8; ks++) {
        uint4 ah[4];
#pragma unroll
        for (int mt = 0; mt < 4; mt++)
            ah[mt] = As[((warp_m * 4 + mt) * 8 + ks) * 32 + lane];
#pragma unroll
        for (int nt = 0; nt < 4; nt++) {
            uint2 bh = Bs2[((warp_n * 4 + nt) * 8 + ks) * 32 + lane];
#pragma unroll
            for (int mt = 0; mt < 4; mt++) mma_f16(d[mt][nt], ah[mt], bh);
        }
    }

    // ---- epilogue2: bias + leaky -> g_h16 ----
    uint32_t* __restrict__ H32 = (uint32_t*)g_h16;
#pragma unroll
    for (int nt = 0; nt < 4; nt++) {
        int c0 = warp_n * 32 + nt * 8 + (lane & 3) * 2;
        float bb0 = b2[c0], bb1 = b2[c0 + 1];
#pragma unroll
        for (int mt = 0; mt < 4; mt++) {
            int r = m0 + warp_m * 64 + mt * 16 + (lane >> 2);
            float v0 = d[mt][nt][0] + bb0, v1 = d[mt][nt][1] + bb1;
            float v2 = d[mt][nt][2] + bb0, v3 = d[mt][nt][3] + bb1;
            v0 = v0 > 0.f ? v0 : SLOPE * v0;
            v1 = v1 > 0.f ? v1 : SLOPE * v1;
            v2 = v2 > 0.f ? v2 : SLOPE * v2;
            v3 = v3 > 0.f ? v3 : SLOPE * v3;
            if (r < NN)     H32[r * 64 + c0 / 2]       = packh2(v0, v1);
            if (r + 8 < NN) H32[(r + 8) * 64 + c0 / 2] = packh2(v2, v3);
        }
    }
}

// ---------------- pooling + pooled-BN + FC (4 graphs per 256-thread block) ---------
__global__ void __launch_bounds__(256) k_pool(const float* __restrict__ fcW,
                                              const float* __restrict__ fcb,
                                              float* __restrict__ out) {
    int grp = threadIdx.x >> 6;          // 0..3
    int t = threadIdx.x & 63;            // col pair 2t,2t+1
    int g = blockIdx.x * 4 + grp;
    int beg = g_gst[g], end = g_gst[g + 1];
    const uint32_t* __restrict__ H32 = (const uint32_t*)g_h16;
    float a0 = 0.f, a1 = 0.f;
    int i = beg;
    for (; i + 4 <= end; i += 4) {
        uint32_t w0 = H32[i * 64 + t];
        uint32_t w1 = H32[(i + 1) * 64 + t];
        uint32_t w2 = H32[(i + 2) * 64 + t];
        uint32_t w3 = H32[(i + 3) * 64 + t];
        float2 f0 = __half22float2(*(__half2*)&w0);
        float2 f1 = __half22float2(*(__half2*)&w1);
        float2 f2 = __half22float2(*(__half2*)&w2);
        float2 f3 = __half22float2(*(__half2*)&w3);
        a0 += (f0.x + f1.x) + (f2.x + f3.x);
        a1 += (f0.y + f1.y) + (f2.y + f3.y);
    }
    for (; i < end; i++) {
        uint32_t v = H32[i * 64 + t];
        float2 f = __half22float2(*(__half2*)&v);
        a0 += f.x; a1 += f.y;
    }
    __shared__ float p[4][128];
    p[grp][2 * t]     = g_ap[2 * t] * a0 + g_cp[2 * t];
    p[grp][2 * t + 1] = g_ap[2 * t + 1] * a1 + g_cp[2 * t + 1];
    __syncthreads();
    float o = fcb[t];
#pragma unroll 4
    for (int k = 0; k < HH; k++) o += p[grp][k] * fcW[k * LAT + t];
    out[g * LAT + t] = o;
}

// ---------------- launcher ----------------
extern "C" void kernel_launch(void* const* d_in, const int* in_sizes, int n_in,
                              void* d_out, int out_size) {
    const float* x     = (const float*)d_in[0];
    const int*   ei    = (const int*)d_in[1];
    const int*   batch = (const int*)d_in[2];
    const float* W1    = (const float*)d_in[3];
    const float* b1    = (const float*)d_in[4];
    const float* g1    = (const float*)d_in[5];
    const float* beta1 = (const float*)d_in[6];
    const float* rm1   = (const float*)d_in[7];
    const float* rv1   = (const float*)d_in[8];
    const float* W2    = (const float*)d_in[9];
    const float* b2    = (const float*)d_in[10];
    const float* bng   = (const float*)d_in[11];
    const float* bnb   = (const float*)d_in[12];
    const float* bnrm  = (const float*)d_in[13];
    const float* bnrv  = (const float*)d_in[14];
    const float* fcW   = (const float*)d_in[15];
    const float* fcb   = (const float*)d_in[16];
    float* out = (float*)d_out;
    const int* src = ei;
    const int* dst = ei + EE;

    const int smem = 98304;
    cudaFuncSetAttribute(k_mlp, cudaFuncAttributeMaxDynamicSharedMemorySize, smem);

    k_setup<<<9458, 256>>>(x, batch, dst, g1, beta1, rm1, rv1,
                           bng, bnb, bnrm, bnrv, W1, W2);
    k_scan<<<NB_SCAN, 1024>>>();
    k_scatter<<<(EE + 255) / 256, 256>>>(src, dst);

    const int gb = (NN + 127) / 128;   // 782
    for (int l = 0; l < LL; l++) {
        k_agg<<<(NN + 7) / 8, 256>>>(l);
        k_mlp<<<gb, 256, smem>>>(b1 + l * HH, b2 + l * HH, l);
    }
    k_pool<<<(GG + 3) / 4, 256>>>(fcW, fcb, out);
}

// round 14
// speedup vs baseline: 1.0334x; 1.0334x over previous
#include <cuda_runtime.h>
#include <cuda_fp16.h>
#include <cstdint>

#define NN 100000
#define EE 1600000
#define HH 128
#define LL 3
#define GG 512
#define LAT 64
#define SLOPE 0.2f
#define BN_EPS 1e-5f
#define NB_SCAN 98   // ceil(NN/1024)

// ---------------- device scratch (all activations fp16) ----------------
__device__ uint2 g_x16[NN * 32];   // fp16 x
__device__ uint2 g_h16[NN * 32];   // fp16 h
__device__ uint2 g_s16[NN * 32];   // fp16 s = h + agg
__device__ int   g_deg[NN];        // INVARIANT: zero at launch entry (re-zeroed in k_scan)
__device__ int   g_rs[NN + 1];
__device__ int   g_cur[NN];
__device__ int   g_col[EE];
__device__ int   g_bsum[128];      // INVARIANT: zero at launch entry (re-zeroed in k_scatter)
__device__ int   g_gst[GG + 1];
__device__ float g_a1[LL * HH];
__device__ float g_c1[LL * HH];
__device__ float g_ap[HH];
__device__ float g_cp[HH];
__device__ uint2 g_wb[6 * 4096];   // fp16 fragment-packed weights, 32KB/matrix

// ---------------- helpers ----------------
__device__ __forceinline__ uint32_t packh2(float a, float b) {
    __half2 h = __float22half2_rn(make_float2(a, b));
    return *(uint32_t*)&h;
}

__device__ __forceinline__ void mma_f16(float* d, const uint4& a, const uint2& b) {
    asm volatile(
        "mma.sync.aligned.m16n8k16.row.col.f32.f16.f16.f32 "
        "{%0,%1,%2,%3},{%4,%5,%6,%7},{%8,%9},{%0,%1,%2,%3};"
        : "+f"(d[0]), "+f"(d[1]), "+f"(d[2]), "+f"(d[3])
        : "r"(a.x), "r"(a.y), "r"(a.z), "r"(a.w), "r"(b.x), "r"(b.y));
}

// ---------------- merged setup + degree histogram ----------------
__global__ void __launch_bounds__(256) k_setup(
    const float* __restrict__ x, const int* __restrict__ batch,
    const int* __restrict__ dst,
    const float* __restrict__ g1, const float* __restrict__ beta1,
    const float* __restrict__ rm1, const float* __restrict__ rv1,
    const float* __restrict__ bng, const float* __restrict__ bnb,
    const float* __restrict__ bnrm, const float* __restrict__ bnrv,
    const float* __restrict__ W1, const float* __restrict__ W2) {
    int b = blockIdx.x, tid = threadIdx.x;
    if (b < 3200) {
        const float4* x4 = (const float4*)x;
#pragma unroll
        for (int i = 0; i < 4; i++) {
            int idx = (b * 256 + tid) * 4 + i;
            if (idx < NN * 32) {
                float4 v = x4[idx];
                g_x16[idx] = make_uint2(packh2(v.x, v.y), packh2(v.z, v.w));
            }
        }
    } else if (b < 9450) {
        int e = (b - 3200) * 256 + tid;
        if (e < EE) atomicAdd(&g_deg[dst[e]], 1);
    } else if (b < 9452) {
        int t = (b - 9450) * 256 + tid;   // 0..511
        if (t < LL * HH) {
            float a = g1[t] * rsqrtf(rv1[t] + BN_EPS);
            g_a1[t] = a;
            g_c1[t] = beta1[t] - a * rm1[t];
        }
        if (t < HH) {
            float a = bng[t] * rsqrtf(bnrv[t] + BN_EPS);
            g_ap[t] = a;
            g_cp[t] = bnb[t] - a * bnrm[t];
        }
        int lo = 0, hi = NN;
        while (lo < hi) { int m = (lo + hi) >> 1; if (batch[m] < t) lo = m + 1; else hi = m; }
        g_gst[t] = lo;
        if (t == 0) g_gst[GG] = NN;
    } else {
        int mat = b - 9452;   // 0..5
        int l = mat >> 1, ph = mat & 1;
        const float* w = (ph ? W2 : W1) + l * HH * HH;
        uint2* outp = &g_wb[mat * 4096];
#pragma unroll
        for (int i = 0; i < 16; i++) {
            int s = tid + i * 256;
            int nt = s >> 8, ks = (s >> 5) & 7, lane = s & 31;
            int k0 = ks * 16 + (lane & 3) * 2;
            int n = nt * 8 + (lane >> 2);
            outp[s] = make_uint2(packh2(w[k0 * HH + n], w[(k0 + 1) * HH + n]),
                                 packh2(w[(k0 + 8) * HH + n], w[(k0 + 9) * HH + n]));
        }
    }
}

// ---------------- single-pass scan (decoupled lookback, 98 resident blocks) --------
__global__ void __launch_bounds__(1024) k_scan() {
    __shared__ int sm[1024];
    __shared__ int carry;
    int t = threadIdx.x, b = blockIdx.x;
    int i = b * 1024 + t;
    int v = (i < NN) ? g_deg[i] : 0;
    sm[t] = v;
    if (t == 0) carry = 0;
    __syncthreads();
    for (int off = 1; off < 1024; off <<= 1) {
        int u = (t >= off) ? sm[t - off] : 0;
        __syncthreads();
        sm[t] += u;
        __syncthreads();
    }
    int incl = sm[t];
    if (t == 1023) atomicExch(&g_bsum[b], sm[1023] + 1);   // publish aggregate+1
    if (t < b) {
        int f;
        do { f = atomicAdd(&g_bsum[t], 0); } while (f == 0);
        atomicAdd(&carry, f - 1);
    }
    __syncthreads();
    int off0 = carry;
    if (i < NN) {
        int inc2 = incl + off0;
        g_rs[i + 1] = inc2;
        g_cur[i] = inc2 - v;
        g_deg[i] = 0;          // restore invariant for next launch
    }
    if (i == 0) g_rs[0] = 0;
}

__global__ void k_scatter(const int* __restrict__ src, const int* __restrict__ dst) {
    if (blockIdx.x < NB_SCAN && threadIdx.x == 0) g_bsum[blockIdx.x] = 0;  // invariant
    int e = blockIdx.x * blockDim.x + threadIdx.x;
    if (e < EE) {
        int p = atomicAdd(&g_cur[dst[e]], 1);
        g_col[p] = src[e];
    }
}

// ---------------- aggregation: warp per node (round-12 base, 8-group fp16 chains) --
__global__ void __launch_bounds__(256) k_agg(int layer) {
    const uint2* __restrict__ h16 = (layer == 0) ? g_x16 : g_h16;
    int w = threadIdx.x >> 5, lane = threadIdx.x & 31;
    int node = blockIdx.x * 8 + w;
    if (node >= NN) return;
    int beg = g_rs[node], end = g_rs[node + 1];
    uint2 sv = h16[node * 32 + lane];
    float2 f0 = __half22float2(*(__half2*)&sv.x);
    float2 f1 = __half22float2(*(__half2*)&sv.y);
    float a0 = f0.x, a1 = f0.y, a2 = f1.x, a3 = f1.y;
    const __half2 hz = __float2half2_rn(0.f);
    for (int j = beg; j < end; j += 32) {
        int cnt = min(32, end - j);
        int idx = (lane < cnt) ? g_col[j + lane] : 0;
        int u = 0;
        // 8-neighbor groups: two interleaved depth-4 fp16 chains per slot
        for (; u + 8 <= cnt; u += 8) {
            __half2 cA = hz, cB = hz, dA = hz, dB = hz;
#pragma unroll
            for (int p = 0; p < 8; p += 2) {
                int ja = __shfl_sync(0xffffffffu, idx, u + p);
                int jb = __shfl_sync(0xffffffffu, idx, u + p + 1);
                uint2 va = h16[ja * 32 + lane];
                uint2 vb = h16[jb * 32 + lane];
                cA = __hadd2(cA, *(__half2*)&va.x);
                dA = __hadd2(dA, *(__half2*)&va.y);
                cB = __hadd2(cB, *(__half2*)&vb.x);
                dB = __hadd2(dB, *(__half2*)&vb.y);
            }
            __half2 hlo = __hadd2(cA, cB);
            __half2 hhi = __hadd2(dA, dB);
            float2 flo = __half22float2(hlo);
            float2 fhi = __half22float2(hhi);
            a0 += flo.x; a1 += flo.y; a2 += fhi.x; a3 += fhi.y;
        }
        // 4-group (round-12 proven)
        for (; u + 4 <= cnt; u += 4) {
            int j0 = __shfl_sync(0xffffffffu, idx, u);
            int j1 = __shfl_sync(0xffffffffu, idx, u + 1);
            int j2 = __shfl_sync(0xffffffffu, idx, u + 2);
            int j3 = __shfl_sync(0xffffffffu, idx, u + 3);
            uint2 v0 = h16[j0 * 32 + lane];
            uint2 v1 = h16[j1 * 32 + lane];
            uint2 v2 = h16[j2 * 32 + lane];
            uint2 v3 = h16[j3 * 32 + lane];
            __half2 hlo = __hadd2(__hadd2(*(__half2*)&v0.x, *(__half2*)&v1.x),
                                  __hadd2(*(__half2*)&v2.x, *(__half2*)&v3.x));
            __half2 hhi = __hadd2(__hadd2(*(__half2*)&v0.y, *(__half2*)&v1.y),
                                  __hadd2(*(__half2*)&v2.y, *(__half2*)&v3.y));
            float2 flo = __half22float2(hlo);
            float2 fhi = __half22float2(hhi);
            a0 += flo.x; a1 += flo.y; a2 += fhi.x; a3 += fhi.y;
        }
        for (; u < cnt; u++) {
            int jj = __shfl_sync(0xffffffffu, idx, u);
            uint2 v = h16[jj * 32 + lane];
            float2 f;
            f = __half22float2(*(__half2*)&v.x); a0 += f.x; a1 += f.y;
            f = __half22float2(*(__half2*)&v.y); a2 += f.x; a3 += f.y;
        }
    }
    g_s16[node * 32 + lane] = make_uint2(packh2(a0, a1), packh2(a2, a3));
}

// ---------------- fused MLP, fp16 single-term HMMA (round-5 proven) -----------------
__global__ void __launch_bounds__(256, 2) k_mlp(const float* __restrict__ b1,
                                                const float* __restrict__ b2, int l) {
    extern __shared__ char sm[];
    uint4* As = (uint4*)sm;
    uint2* Bs1 = (uint2*)(sm + 32768);
    uint2* Bs2 = (uint2*)(sm + 65536);

    int tid = threadIdx.x, wid = tid >> 5, lane = tid & 31;
    int warp_m = wid >> 2, warp_n = wid & 3;
    int m0 = blockIdx.x * 128;

    {
        const uint4* src = (const uint4*)&g_wb[l * 8192];
        uint4* dst = (uint4*)Bs1;
#pragma unroll
        for (int i = 0; i < 16; i++) dst[tid + i * 256] = src[tid + i * 256];
    }

    const uint32_t* __restrict__ S32 = (const uint32_t*)g_s16;
#pragma unroll
    for (int i = 0; i < 8; i++) {
        int s = tid + i * 256;
        int mt = s >> 8, ks = (s >> 5) & 7, ln = s & 31;
        int r = m0 + mt * 16 + (ln >> 2);
        int cp = ks * 8 + (ln & 3);
        uint4 a = make_uint4(0u, 0u, 0u, 0u);
        if (r < NN)     { a.x = S32[r * 64 + cp];       a.z = S32[r * 64 + cp + 4]; }
        if (r + 8 < NN) { a.y = S32[(r + 8) * 64 + cp]; a.w = S32[(r + 8) * 64 + cp + 4]; }
        As[s] = a;
    }
    __syncthreads();

    float d[4][4][4];
#pragma unroll
    for (int mt = 0; mt < 4; mt++)
#pragma unroll
        for (int nt = 0; nt < 4; nt++)
#pragma unroll
            for (int q = 0; q < 4; q++) d[mt][nt][q] = 0.f;

    // ---- GEMM1 ----
#pragma unroll 1
    for (int ks = 0; ks < 8; ks++) {
        uint4 ah[4];
#pragma unroll
        for (int mt = 0; mt < 4; mt++)
            ah[mt] = As[((warp_m * 4 + mt) * 8 + ks) * 32 + lane];
#pragma unroll
        for (int nt = 0; nt < 4; nt++) {
            uint2 bh = Bs1[((warp_n * 4 + nt) * 8 + ks) * 32 + lane];
#pragma unroll
            for (int mt = 0; mt < 4; mt++) mma_f16(d[mt][nt], ah[mt], bh);
        }
    }

    // ---- epilogue1 -> GEMM2 A-fragments (in-register) ----
    uint4 tf[4][2];
    {
        float aa[8], cc[8], bb[8];
#pragma unroll
        for (int j = 0; j < 8; j++) {
            int c = warp_n * 32 + (j >> 1) * 8 + (lane & 3) * 2 + (j & 1);
            bb[j] = b1[c];
            aa[j] = g_a1[l * HH + c];
            cc[j] = g_c1[l * HH + c];
        }
#pragma unroll
        for (int mt = 0; mt < 4; mt++) {
#pragma unroll
            for (int nt = 0; nt < 4; nt++) {
#pragma unroll
                for (int q = 0; q < 4; q++) {
                    float v = d[mt][nt][q] + bb[nt * 2 + (q & 1)];
                    v = v > 0.f ? v : SLOPE * v;
                    d[mt][nt][q] = aa[nt * 2 + (q & 1)] * v + cc[nt * 2 + (q & 1)];
                }
            }
#pragma unroll
            for (int kp = 0; kp < 2; kp++) {
                tf[mt][kp].x = packh2(d[mt][2 * kp][0],     d[mt][2 * kp][1]);
                tf[mt][kp].y = packh2(d[mt][2 * kp][2],     d[mt][2 * kp][3]);
                tf[mt][kp].z = packh2(d[mt][2 * kp + 1][0], d[mt][2 * kp + 1][1]);
                tf[mt][kp].w = packh2(d[mt][2 * kp + 1][2], d[mt][2 * kp + 1][3]);
            }
        }
    }
    __syncthreads();
#pragma unroll
    for (int mt = 0; mt < 4; mt++)
#pragma unroll
        for (int kp = 0; kp < 2; kp++)
            As[((warp_m * 4 + mt) * 8 + warp_n * 2 + kp) * 32 + lane] = tf[mt][kp];
    __syncthreads();

#pragma unroll
    for (int mt = 0; mt < 4; mt++)
#pragma unroll
        for (int nt = 0; nt < 4; nt++)
#pragma unroll
            for (int q = 0; q < 4; q++) d[mt][nt][q] = 0.f;

    // ---- GEMM2 ----
#pragma unroll 1
    for (int ks = 0; ks < 8; ks++) {
        uint4 ah[4];
#pragma unroll
        for (int mt = 0; mt < 4; mt++)
            ah[mt] = As[((warp_m * 4 + mt) * 8 + ks) * 32 + lane];
#pragma unroll
        for (int nt = 0; nt < 4; nt++) {
            uint2 bh = Bs2[((warp_n * 4 + nt) * 8 + ks) * 32 + lane];
#pragma unroll
            for (int mt = 0; mt < 4; mt++) mma_f16(d[mt][nt], ah[mt], bh);
        }
    }

    // ---- epilogue2: bias + leaky -> g_h16 ----
    uint32_t* __restrict__ H32 = (uint32_t*)g_h16;
#pragma unroll
    for (int nt = 0; nt < 4; nt++) {
        int c0 = warp_n * 32 + nt * 8 + (lane & 3) * 2;
        float bb0 = b2[c0], bb1 = b2[c0 + 1];
#pragma unroll
        for (int mt = 0; mt < 4; mt++) {
            int r = m0 + warp_m * 64 + mt * 16 + (lane >> 2);
            float v0 = d[mt][nt][0] + bb0, v1 = d[mt][nt][1] + bb1;
            float v2 = d[mt][nt][2] + bb0, v3 = d[mt][nt][3] + bb1;
            v0 = v0 > 0.f ? v0 : SLOPE * v0;
            v1 = v1 > 0.f ? v1 : SLOPE * v1;
            v2 = v2 > 0.f ? v2 : SLOPE * v2;
            v3 = v3 > 0.f ? v3 : SLOPE * v3;
            if (r < NN)     H32[r * 64 + c0 / 2]       = packh2(v0, v1);
            if (r + 8 < NN) H32[(r + 8) * 64 + c0 / 2] = packh2(v2, v3);
        }
    }
}

// ---------------- pooling + pooled-BN + FC (4 graphs per 256-thread block) ---------
__global__ void __launch_bounds__(256) k_pool(const float* __restrict__ fcW,
                                              const float* __restrict__ fcb,
                                              float* __restrict__ out) {
    int grp = threadIdx.x >> 6;          // 0..3
    int t = threadIdx.x & 63;            // col pair 2t,2t+1
    int g = blockIdx.x * 4 + grp;
    int beg = g_gst[g], end = g_gst[g + 1];
    const uint32_t* __restrict__ H32 = (const uint32_t*)g_h16;
    float a0 = 0.f, a1 = 0.f;
    int i = beg;
    for (; i + 4 <= end; i += 4) {
        uint32_t w0 = H32[i * 64 + t];
        uint32_t w1 = H32[(i + 1) * 64 + t];
        uint32_t w2 = H32[(i + 2) * 64 + t];
        uint32_t w3 = H32[(i + 3) * 64 + t];
        float2 f0 = __half22float2(*(__half2*)&w0);
        float2 f1 = __half22float2(*(__half2*)&w1);
        float2 f2 = __half22float2(*(__half2*)&w2);
        float2 f3 = __half22float2(*(__half2*)&w3);
        a0 += (f0.x + f1.x) + (f2.x + f3.x);
        a1 += (f0.y + f1.y) + (f2.y + f3.y);
    }
    for (; i < end; i++) {
        uint32_t v = H32[i * 64 + t];
        float2 f = __half22float2(*(__half2*)&v);
        a0 += f.x; a1 += f.y;
    }
    __shared__ float p[4][128];
    p[grp][2 * t]     = g_ap[2 * t] * a0 + g_cp[2 * t];
    p[grp][2 * t + 1] = g_ap[2 * t + 1] * a1 + g_cp[2 * t + 1];
    __syncthreads();
    float o = fcb[t];
#pragma unroll 4
    for (int k = 0; k < HH; k++) o += p[grp][k] * fcW[k * LAT + t];
    out[g * LAT + t] = o;
}

// ---------------- launcher ----------------
extern "C" void kernel_launch(void* const* d_in, const int* in_sizes, int n_in,
                              void* d_out, int out_size) {
    const float* x     = (const float*)d_in[0];
    const int*   ei    = (const int*)d_in[1];
    const int*   batch = (const int*)d_in[2];
    const float* W1    = (const float*)d_in[3];
    const float* b1    = (const float*)d_in[4];
    const float* g1    = (const float*)d_in[5];
    const float* beta1 = (const float*)d_in[6];
    const float* rm1   = (const float*)d_in[7];
    const float* rv1   = (const float*)d_in[8];
    const float* W2    = (const float*)d_in[9];
    const float* b2    = (const float*)d_in[10];
    const float* bng   = (const float*)d_in[11];
    const float* bnb   = (const float*)d_in[12];
    const float* bnrm  = (const float*)d_in[13];
    const float* bnrv  = (const float*)d_in[14];
    const float* fcW   = (const float*)d_in[15];
    const float* fcb   = (const float*)d_in[16];
    float* out = (float*)d_out;
    const int* src = ei;
    const int* dst = ei + EE;

    const int smem = 98304;
    cudaFuncSetAttribute(k_mlp, cudaFuncAttributeMaxDynamicSharedMemorySize, smem);

    k_setup<<<9458, 256>>>(x, batch, dst, g1, beta1, rm1, rv1,
                           bng, bnb, bnrm, bnrv, W1, W2);
    k_scan<<<NB_SCAN, 1024>>>();
    k_scatter<<<(EE + 255) / 256, 256>>>(src, dst);

    const int gb = (NN + 127) / 128;   // 782
    for (int l = 0; l < LL; l++) {
        k_agg<<<(NN + 7) / 8, 256>>>(l);
        k_mlp<<<gb, 256, smem>>>(b1 + l * HH, b2 + l * HH, l);
    }
    k_pool<<<(GG + 3) / 4, 256>>>(fcW, fcb, out);
}

// round 15
// speedup vs baseline: 1.0757x; 1.0410x over previous
#include <cuda_runtime.h>
#include <cuda_fp16.h>
#include <cstdint>

#define NN 100000
#define EE 1600000
#define HH 128
#define LL 3
#define GG 512
#define LAT 64
#define SLOPE 0.2f
#define BN_EPS 1e-5f
#define NB_SCAN 98   // ceil(NN/1024)

// ---------------- device scratch (all activations fp16) ----------------
__device__ uint2 g_x16[NN * 32];   // fp16 x
__device__ uint2 g_h16[NN * 32];   // fp16 h
__device__ uint2 g_s16[NN * 32];   // fp16 s = h + agg
__device__ int   g_deg[NN];        // INVARIANT: zero at launch entry (re-zeroed in k_scan)
__device__ int   g_rs[NN + 1];
__device__ int   g_cur[NN];
__device__ int   g_col[EE];
__device__ int   g_bsum[128];      // INVARIANT: zero at launch entry (re-zeroed in k_scatter)
__device__ int   g_gst[GG + 1];
__device__ float g_a1[LL * HH];
__device__ float g_c1[LL * HH];
__device__ float g_ap[HH];
__device__ float g_cp[HH];
__device__ uint2 g_wb[6 * 4096];   // fp16 fragment-packed weights, 32KB/matrix

// ---------------- helpers ----------------
__device__ __forceinline__ uint32_t packh2(float a, float b) {
    __half2 h = __float22half2_rn(make_float2(a, b));
    return *(uint32_t*)&h;
}

__device__ __forceinline__ void mma_f16(float* d, const uint4& a, const uint2& b) {
    asm volatile(
        "mma.sync.aligned.m16n8k16.row.col.f32.f16.f16.f32 "
        "{%0,%1,%2,%3},{%4,%5,%6,%7},{%8,%9},{%0,%1,%2,%3};"
        : "+f"(d[0]), "+f"(d[1]), "+f"(d[2]), "+f"(d[3])
        : "r"(a.x), "r"(a.y), "r"(a.z), "r"(a.w), "r"(b.x), "r"(b.y));
}

// ---------------- merged setup + degree histogram ----------------
__global__ void __launch_bounds__(256) k_setup(
    const float* __restrict__ x, const int* __restrict__ batch,
    const int* __restrict__ dst,
    const float* __restrict__ g1, const float* __restrict__ beta1,
    const float* __restrict__ rm1, const float* __restrict__ rv1,
    const float* __restrict__ bng, const float* __restrict__ bnb,
    const float* __restrict__ bnrm, const float* __restrict__ bnrv,
    const float* __restrict__ W1, const float* __restrict__ W2) {
    int b = blockIdx.x, tid = threadIdx.x;
    if (b < 3200) {
        const float4* x4 = (const float4*)x;
#pragma unroll
        for (int i = 0; i < 4; i++) {
            int idx = (b * 256 + tid) * 4 + i;
            if (idx < NN * 32) {
                float4 v = x4[idx];
                g_x16[idx] = make_uint2(packh2(v.x, v.y), packh2(v.z, v.w));
            }
        }
    } else if (b < 9450) {
        int e = (b - 3200) * 256 + tid;
        if (e < EE) atomicAdd(&g_deg[dst[e]], 1);
    } else if (b < 9452) {
        int t = (b - 9450) * 256 + tid;   // 0..511
        if (t < LL * HH) {
            float a = g1[t] * rsqrtf(rv1[t] + BN_EPS);
            g_a1[t] = a;
            g_c1[t] = beta1[t] - a * rm1[t];
        }
        if (t < HH) {
            float a = bng[t] * rsqrtf(bnrv[t] + BN_EPS);
            g_ap[t] = a;
            g_cp[t] = bnb[t] - a * bnrm[t];
        }
        int lo = 0, hi = NN;
        while (lo < hi) { int m = (lo + hi) >> 1; if (batch[m] < t) lo = m + 1; else hi = m; }
        g_gst[t] = lo;
        if (t == 0) g_gst[GG] = NN;
    } else {
        int mat = b - 9452;   // 0..5
        int l = mat >> 1, ph = mat & 1;
        const float* w = (ph ? W2 : W1) + l * HH * HH;
        uint2* outp = &g_wb[mat * 4096];
#pragma unroll
        for (int i = 0; i < 16; i++) {
            int s = tid + i * 256;
            int nt = s >> 8, ks = (s >> 5) & 7, lane = s & 31;
            int k0 = ks * 16 + (lane & 3) * 2;
            int n = nt * 8 + (lane >> 2);
            outp[s] = make_uint2(packh2(w[k0 * HH + n], w[(k0 + 1) * HH + n]),
                                 packh2(w[(k0 + 8) * HH + n], w[(k0 + 9) * HH + n]));
        }
    }
}

// ---------------- single-pass scan (decoupled lookback, 98 resident blocks) --------
__global__ void __launch_bounds__(1024) k_scan() {
    __shared__ int sm[1024];
    __shared__ int carry;
    int t = threadIdx.x, b = blockIdx.x;
    int i = b * 1024 + t;
    int v = (i < NN) ? g_deg[i] : 0;
    sm[t] = v;
    if (t == 0) carry = 0;
    __syncthreads();
    for (int off = 1; off < 1024; off <<= 1) {
        int u = (t >= off) ? sm[t - off] : 0;
        __syncthreads();
        sm[t] += u;
        __syncthreads();
    }
    int incl = sm[t];
    if (t == 1023) atomicExch(&g_bsum[b], sm[1023] + 1);   // publish aggregate+1
    if (t < b) {
        int f;
        do { f = atomicAdd(&g_bsum[t], 0); } while (f == 0);
        atomicAdd(&carry, f - 1);
    }
    __syncthreads();
    int off0 = carry;
    if (i < NN) {
        int inc2 = incl + off0;
        g_rs[i + 1] = inc2;
        g_cur[i] = inc2 - v;
        g_deg[i] = 0;          // restore invariant for next launch
    }
    if (i == 0) g_rs[0] = 0;
}

__global__ void k_scatter(const int* __restrict__ src, const int* __restrict__ dst) {
    if (blockIdx.x < NB_SCAN && threadIdx.x == 0) g_bsum[blockIdx.x] = 0;  // invariant
    int e = blockIdx.x * blockDim.x + threadIdx.x;
    if (e < EE) {
        int p = atomicAdd(&g_cur[dst[e]], 1);
        g_col[p] = src[e];
    }
}

// ---------------- aggregation: warp per node, half2 group accumulation -------------
__global__ void __launch_bounds__(256) k_agg(int layer) {
    const uint2* __restrict__ h16 = (layer == 0) ? g_x16 : g_h16;
    int w = threadIdx.x >> 5, lane = threadIdx.x & 31;
    int node = blockIdx.x * 8 + w;
    if (node >= NN) return;
    int beg = g_rs[node], end = g_rs[node + 1];
    uint2 sv = h16[node * 32 + lane];
    float2 f0 = __half22float2(*(__half2*)&sv.x);
    float2 f1 = __half22float2(*(__half2*)&sv.y);
    float a0 = f0.x, a1 = f0.y, a2 = f1.x, a3 = f1.y;
    const __half2 hz = __float2half2_rn(0.f);
    for (int j = beg; j < end; j += 32) {
        int cnt = min(32, end - j);
        int idx = (lane < cnt) ? g_col[j + lane] : 0;
        int u = 0;
        for (; u + 4 <= cnt; u += 4) {
            int j0 = __shfl_sync(0xffffffffu, idx, u);
            int j1 = __shfl_sync(0xffffffffu, idx, u + 1);
            int j2 = __shfl_sync(0xffffffffu, idx, u + 2);
            int j3 = __shfl_sync(0xffffffffu, idx, u + 3);
            uint2 v0 = h16[j0 * 32 + lane];
            uint2 v1 = h16[j1 * 32 + lane];
            uint2 v2 = h16[j2 * 32 + lane];
            uint2 v3 = h16[j3 * 32 + lane];
            // fp16 accumulation within the 4-group (HADD2 x8), flush to fp32
            __half2 hlo = __hadd2(__hadd2(*(__half2*)&v0.x, *(__half2*)&v1.x),
                                  __hadd2(*(__half2*)&v2.x, *(__half2*)&v3.x));
            __half2 hhi = __hadd2(__hadd2(*(__half2*)&v0.y, *(__half2*)&v1.y),
                                  __hadd2(*(__half2*)&v2.y, *(__half2*)&v3.y));
            float2 flo = __half22float2(hlo);
            float2 fhi = __half22float2(hhi);
            a0 += flo.x; a1 += flo.y; a2 += fhi.x; a3 += fhi.y;
        }
        for (; u < cnt; u++) {
            int jj = __shfl_sync(0xffffffffu, idx, u);
            uint2 v = h16[jj * 32 + lane];
            float2 f;
            f = __half22float2(*(__half2*)&v.x); a0 += f.x; a1 += f.y;
            f = __half22float2(*(__half2*)&v.y); a2 += f.x; a3 += f.y;
        }
    }
    (void)hz;
    g_s16[node * 32 + lane] = make_uint2(packh2(a0, a1), packh2(a2, a3));
}

// ---------------- fused MLP, fp16 single-term HMMA (round-5 proven) -----------------
__global__ void __launch_bounds__(256, 2) k_mlp(const float* __restrict__ b1,
                                                const float* __restrict__ b2, int l) {
    extern __shared__ char sm[];
    uint4* As = (uint4*)sm;
    uint2* Bs1 = (uint2*)(sm + 32768);
    uint2* Bs2 = (uint2*)(sm + 65536);

    int tid = threadIdx.x, wid = tid >> 5, lane = tid & 31;
    int warp_m = wid >> 2, warp_n = wid & 3;
    int m0 = blockIdx.x * 128;

    {
        const uint4* src = (const uint4*)&g_wb[l * 8192];
        uint4* dst = (uint4*)Bs1;
#pragma unroll
        for (int i = 0; i < 16; i++) dst[tid + i * 256] = src[tid + i * 256];
    }

    const uint32_t* __restrict__ S32 = (const uint32_t*)g_s16;
#pragma unroll
    for (int i = 0; i < 8; i++) {
        int s = tid + i * 256;
        int mt = s >> 8, ks = (s >> 5) & 7, ln = s & 31;
        int r = m0 + mt * 16 + (ln >> 2);
        int cp = ks * 8 + (ln & 3);
        uint4 a = make_uint4(0u, 0u, 0u, 0u);
        if (r < NN)     { a.x = S32[r * 64 + cp];       a.z = S32[r * 64 + cp + 4]; }
        if (r + 8 < NN) { a.y = S32[(r + 8) * 64 + cp]; a.w = S32[(r + 8) * 64 + cp + 4]; }
        As[s] = a;
    }
    __syncthreads();

    float d[4][4][4];
#pragma unroll
    for (int mt = 0; mt < 4; mt++)
#pragma unroll
        for (int nt = 0; nt < 4; nt++)
#pragma unroll
            for (int q = 0; q < 4; q++) d[mt][nt][q] = 0.f;

    // ---- GEMM1 ----
#pragma unroll 1
    for (int ks = 0; ks < 8; ks++) {
        uint4 ah[4];
#pragma unroll
        for (int mt = 0; mt < 4; mt++)
            ah[mt] = As[((warp_m * 4 + mt) * 8 + ks) * 32 + lane];
#pragma unroll
        for (int nt = 0; nt < 4; nt++) {
            uint2 bh = Bs1[((warp_n * 4 + nt) * 8 + ks) * 32 + lane];
#pragma unroll
            for (int mt = 0; mt < 4; mt++) mma_f16(d[mt][nt], ah[mt], bh);
        }
    }

    // ---- epilogue1 -> GEMM2 A-fragments (in-register) ----
    uint4 tf[4][2];
    {
        float aa[8], cc[8], bb[8];
#pragma unroll
        for (int j = 0; j < 8; j++) {
            int c = warp_n * 32 + (j >> 1) * 8 + (lane & 3) * 2 + (j & 1);
            bb[j] = b1[c];
            aa[j] = g_a1[l * HH + c];
            cc[j] = g_c1[l * HH + c];
        }
#pragma unroll
        for (int mt = 0; mt < 4; mt++) {
#pragma unroll
            for (int nt = 0; nt < 4; nt++) {
#pragma unroll
                for (int q = 0; q < 4; q++) {
                    float v = d[mt][nt][q] + bb[nt * 2 + (q & 1)];
                    v = v > 0.f ? v : SLOPE * v;
                    d[mt][nt][q] = aa[nt * 2 + (q & 1)] * v + cc[nt * 2 + (q & 1)];
                }
            }
#pragma unroll
            for (int kp = 0; kp < 2; kp++) {
                tf[mt][kp].x = packh2(d[mt][2 * kp][0],     d[mt][2 * kp][1]);
                tf[mt][kp].y = packh2(d[mt][2 * kp][2],     d[mt][2 * kp][3]);
                tf[mt][kp].z = packh2(d[mt][2 * kp + 1][0], d[mt][2 * kp + 1][1]);
                tf[mt][kp].w = packh2(d[mt][2 * kp + 1][2], d[mt][2 * kp + 1][3]);
            }
        }
    }
    __syncthreads();
#pragma unroll
    for (int mt = 0; mt < 4; mt++)
#pragma unroll
        for (int kp = 0; kp < 2; kp++)
            As[((warp_m * 4 + mt) * 8 + warp_n * 2 + kp) * 32 + lane] = tf[mt][kp];
    __syncthreads();

#pragma unroll
    for (int mt = 0; mt < 4; mt++)
#pragma unroll
        for (int nt = 0; nt < 4; nt++)
#pragma unroll
            for (int q = 0; q < 4; q++) d[mt][nt][q] = 0.f;

    // ---- GEMM2 ----
#pragma unroll 1
    for (int ks = 0; ks < 8; ks++) {
        uint4 ah[4];
#pragma unroll
        for (int mt = 0; mt < 4; mt++)
            ah[mt] = As[((warp_m * 4 + mt) * 8 + ks) * 32 + lane];
#pragma unroll
        for (int nt = 0; nt < 4; nt++) {
            uint2 bh = Bs2[((warp_n * 4 + nt) * 8 + ks) * 32 + lane];
#pragma unroll
            for (int mt = 0; mt < 4; mt++) mma_f16(d[mt][nt], ah[mt], bh);
        }
    }

    // ---- epilogue2: bias + leaky -> g_h16 ----
    uint32_t* __restrict__ H32 = (uint32_t*)g_h16;
#pragma unroll
    for (int nt = 0; nt < 4; nt++) {
        int c0 = warp_n * 32 + nt * 8 + (lane & 3) * 2;
        float bb0 = b2[c0], bb1 = b2[c0 + 1];
#pragma unroll
        for (int mt = 0; mt < 4; mt++) {
            int r = m0 + warp_m * 64 + mt * 16 + (lane >> 2);
            float v0 = d[mt][nt][0] + bb0, v1 = d[mt][nt][1] + bb1;
            float v2 = d[mt][nt][2] + bb0, v3 = d[mt][nt][3] + bb1;
            v0 = v0 > 0.f ? v0 : SLOPE * v0;
            v1 = v1 > 0.f ? v1 : SLOPE * v1;
            v2 = v2 > 0.f ? v2 : SLOPE * v2;
            v3 = v3 > 0.f ? v3 : SLOPE * v3;
            if (r < NN)     H32[r * 64 + c0 / 2]       = packh2(v0, v1);
            if (r + 8 < NN) H32[(r + 8) * 64 + c0 / 2] = packh2(v2, v3);
        }
    }
}

// ---------------- pooling + pooled-BN + FC (4 graphs per 256-thread block) ---------
__global__ void __launch_bounds__(256) k_pool(const float* __restrict__ fcW,
                                              const float* __restrict__ fcb,
                                              float* __restrict__ out) {
    int grp = threadIdx.x >> 6;          // 0..3
    int t = threadIdx.x & 63;            // col pair 2t,2t+1
    int g = blockIdx.x * 4 + grp;
    int beg = g_gst[g], end = g_gst[g + 1];
    const uint32_t* __restrict__ H32 = (const uint32_t*)g_h16;
    float a0 = 0.f, a1 = 0.f;
    int i = beg;
    for (; i + 4 <= end; i += 4) {
        uint32_t w0 = H32[i * 64 + t];
        uint32_t w1 = H32[(i + 1) * 64 + t];
        uint32_t w2 = H32[(i + 2) * 64 + t];
        uint32_t w3 = H32[(i + 3) * 64 + t];
        float2 f0 = __half22float2(*(__half2*)&w0);
        float2 f1 = __half22float2(*(__half2*)&w1);
        float2 f2 = __half22float2(*(__half2*)&w2);
        float2 f3 = __half22float2(*(__half2*)&w3);
        a0 += (f0.x + f1.x) + (f2.x + f3.x);
        a1 += (f0.y + f1.y) + (f2.y + f3.y);
    }
    for (; i < end; i++) {
        uint32_t v = H32[i * 64 + t];
        float2 f = __half22float2(*(__half2*)&v);
        a0 += f.x; a1 += f.y;
    }
    __shared__ float p[4][128];
    p[grp][2 * t]     = g_ap[2 * t] * a0 + g_cp[2 * t];
    p[grp][2 * t + 1] = g_ap[2 * t + 1] * a1 + g_cp[2 * t + 1];
    __syncthreads();
    float o = fcb[t];
#pragma unroll 4
    for (int k = 0; k < HH; k++) o += p[grp][k] * fcW[k * LAT + t];
    out[g * LAT + t] = o;
}

// ---------------- launcher ----------------
extern "C" void kernel_launch(void* const* d_in, const int* in_sizes, int n_in,
                              void* d_out, int out_size) {
    const float* x     = (const float*)d_in[0];
    const int*   ei    = (const int*)d_in[1];
    const int*   batch = (const int*)d_in[2];
    const float* W1    = (const float*)d_in[3];
    const float* b1    = (const float*)d_in[4];
    const float* g1    = (const float*)d_in[5];
    const float* beta1 = (const float*)d_in[6];
    const float* rm1   = (const float*)d_in[7];
    const float* rv1   = (const float*)d_in[8];
    const float* W2    = (const float*)d_in[9];
    const float* b2    = (const float*)d_in[10];
    const float* bng   = (const float*)d_in[11];
    const float* bnb   = (const float*)d_in[12];
    const float* bnrm  = (const float*)d_in[13];
    const float* bnrv  = (const float*)d_in[14];
    const float* fcW   = (const float*)d_in[15];
    const float* fcb   = (const float*)d_in[16];
    float* out = (float*)d_out;
    const int* src = ei;
    const int* dst = ei + EE;

    const int smem = 98304;
    cudaFuncSetAttribute(k_mlp, cudaFuncAttributeMaxDynamicSharedMemorySize, smem);

    k_setup<<<9458, 256>>>(x, batch, dst, g1, beta1, rm1, rv1,
                           bng, bnb, bnrm, bnrv, W1, W2);
    k_scan<<<NB_SCAN, 1024>>>();
    k_scatter<<<(EE + 255) / 256, 256>>>(src, dst);

    const int gb = (NN + 127) / 128;   // 782
    for (int l = 0; l < LL; l++) {
        k_agg<<<(NN + 7) / 8, 256>>>(l);
        k_mlp<<<gb, 256, smem>>>(b1 + l * HH, b2 + l * HH, l);
    }
    k_pool<<<(GG + 3) / 4, 256>>>(fcW, fcb, out);
}

// round 16
// speedup vs baseline: 1.0823x; 1.0061x over previous
#include <cuda_runtime.h>
#include <cuda_fp16.h>
#include <cstdint>

#define NN 100000
#define EE 1600000
#define HH 128
#define LL 3
#define GG 512
#define LAT 64
#define SLOPE 0.2f
#define BN_EPS 1e-5f
#define NB_SCAN 98   // ceil(NN/1024)

// ---------------- device scratch (all activations fp16) ----------------
__device__ uint2 g_x16[NN * 32];   // fp16 x
__device__ uint2 g_h16[NN * 32];   // fp16 h
__device__ uint2 g_s16[NN * 32];   // fp16 s = h + agg
__device__ int   g_deg[NN];        // INVARIANT: zero at launch entry (re-zeroed in k_scan)
__device__ int   g_rs[NN + 1];
__device__ int   g_rank[EE];       // per-edge rank within its dst bucket (from hist)
__device__ int   g_col[EE];
__device__ int   g_bsum[128];      // INVARIANT: zero at launch entry (re-zeroed in k_scatter)
__device__ int   g_gst[GG + 1];
__device__ float g_a1[LL * HH];
__device__ float g_c1[LL * HH];
__device__ float g_ap[HH];
__device__ float g_cp[HH];
__device__ uint2 g_wb[6 * 4096];   // fp16 fragment-packed weights, 32KB/matrix

// ---------------- helpers ----------------
__device__ __forceinline__ uint32_t packh2(float a, float b) {
    __half2 h = __float22half2_rn(make_float2(a, b));
    return *(uint32_t*)&h;
}

__device__ __forceinline__ void mma_f16(float* d, const uint4& a, const uint2& b) {
    asm volatile(
        "mma.sync.aligned.m16n8k16.row.col.f32.f16.f16.f32 "
        "{%0,%1,%2,%3},{%4,%5,%6,%7},{%8,%9},{%0,%1,%2,%3};"
        : "+f"(d[0]), "+f"(d[1]), "+f"(d[2]), "+f"(d[3])
        : "r"(a.x), "r"(a.y), "r"(a.z), "r"(a.w), "r"(b.x), "r"(b.y));
}

// ---------------- merged setup + degree histogram (keeps rank) ----------------
__global__ void __launch_bounds__(256) k_setup(
    const float* __restrict__ x, const int* __restrict__ batch,
    const int* __restrict__ dst,
    const float* __restrict__ g1, const float* __restrict__ beta1,
    const float* __restrict__ rm1, const float* __restrict__ rv1,
    const float* __restrict__ bng, const float* __restrict__ bnb,
    const float* __restrict__ bnrm, const float* __restrict__ bnrv,
    const float* __restrict__ W1, const float* __restrict__ W2) {
    int b = blockIdx.x, tid = threadIdx.x;
    if (b < 3200) {
        const float4* x4 = (const float4*)x;
#pragma unroll
        for (int i = 0; i < 4; i++) {
            int idx = (b * 256 + tid) * 4 + i;
            if (idx < NN * 32) {
                float4 v = x4[idx];
                g_x16[idx] = make_uint2(packh2(v.x, v.y), packh2(v.z, v.w));
            }
        }
    } else if (b < 9450) {
        int e = (b - 3200) * 256 + tid;
        if (e < EE) g_rank[e] = atomicAdd(&g_deg[dst[e]], 1);
    } else if (b < 9452) {
        int t = (b - 9450) * 256 + tid;   // 0..511
        if (t < LL * HH) {
            float a = g1[t] * rsqrtf(rv1[t] + BN_EPS);
            g_a1[t] = a;
            g_c1[t] = beta1[t] - a * rm1[t];
        }
        if (t < HH) {
            float a = bng[t] * rsqrtf(bnrv[t] + BN_EPS);
            g_ap[t] = a;
            g_cp[t] = bnb[t] - a * bnrm[t];
        }
        int lo = 0, hi = NN;
        while (lo < hi) { int m = (lo + hi) >> 1; if (batch[m] < t) lo = m + 1; else hi = m; }
        g_gst[t] = lo;
        if (t == 0) g_gst[GG] = NN;
    } else {
        int mat = b - 9452;   // 0..5
        int l = mat >> 1, ph = mat & 1;
        const float* w = (ph ? W2 : W1) + l * HH * HH;
        uint2* outp = &g_wb[mat * 4096];
#pragma unroll
        for (int i = 0; i < 16; i++) {
            int s = tid + i * 256;
            int nt = s >> 8, ks = (s >> 5) & 7, lane = s & 31;
            int k0 = ks * 16 + (lane & 3) * 2;
            int n = nt * 8 + (lane >> 2);
            outp[s] = make_uint2(packh2(w[k0 * HH + n], w[(k0 + 1) * HH + n]),
                                 packh2(w[(k0 + 8) * HH + n], w[(k0 + 9) * HH + n]));
        }
    }
}

// ---------------- single-pass scan (decoupled lookback, 98 resident blocks) --------
__global__ void __launch_bounds__(1024) k_scan() {
    __shared__ int sm[1024];
    __shared__ int carry;
    int t = threadIdx.x, b = blockIdx.x;
    int i = b * 1024 + t;
    int v = (i < NN) ? g_deg[i] : 0;
    sm[t] = v;
    if (t == 0) carry = 0;
    __syncthreads();
    for (int off = 1; off < 1024; off <<= 1) {
        int u = (t >= off) ? sm[t - off] : 0;
        __syncthreads();
        sm[t] += u;
        __syncthreads();
    }
    int incl = sm[t];
    if (t == 1023) atomicExch(&g_bsum[b], sm[1023] + 1);   // publish aggregate+1
    if (t < b) {
        int f;
        do { f = atomicAdd(&g_bsum[t], 0); } while (f == 0);
        atomicAdd(&carry, f - 1);
    }
    __syncthreads();
    int off0 = carry;
    if (i < NN) {
        g_rs[i + 1] = incl + off0;
        g_deg[i] = 0;          // restore invariant for next launch
    }
    if (i == 0) g_rs[0] = 0;
}

// ---------------- scatter: atomic-free (rank precomputed in hist) ----------------
__global__ void k_scatter(const int* __restrict__ src, const int* __restrict__ dst) {
    if (blockIdx.x < NB_SCAN && threadIdx.x == 0) g_bsum[blockIdx.x] = 0;  // invariant
    int e = blockIdx.x * blockDim.x + threadIdx.x;
    if (e < EE) {
        int d = dst[e];
        g_col[g_rs[d] + g_rank[e]] = src[e];
    }
}

// ---------------- aggregation: warp per node, half2 group accumulation -------------
__global__ void __launch_bounds__(256) k_agg(int layer) {
    const uint2* __restrict__ h16 = (layer == 0) ? g_x16 : g_h16;
    int w = threadIdx.x >> 5, lane = threadIdx.x & 31;
    int node = blockIdx.x * 8 + w;
    if (node >= NN) return;
    int beg = g_rs[node], end = g_rs[node + 1];
    uint2 sv = h16[node * 32 + lane];
    float2 f0 = __half22float2(*(__half2*)&sv.x);
    float2 f1 = __half22float2(*(__half2*)&sv.y);
    float a0 = f0.x, a1 = f0.y, a2 = f1.x, a3 = f1.y;
    const __half2 hz = __float2half2_rn(0.f);
    for (int j = beg; j < end; j += 32) {
        int cnt = min(32, end - j);
        int idx = (lane < cnt) ? g_col[j + lane] : 0;
        int u = 0;
        for (; u + 4 <= cnt; u += 4) {
            int j0 = __shfl_sync(0xffffffffu, idx, u);
            int j1 = __shfl_sync(0xffffffffu, idx, u + 1);
            int j2 = __shfl_sync(0xffffffffu, idx, u + 2);
            int j3 = __shfl_sync(0xffffffffu, idx, u + 3);
            uint2 v0 = h16[j0 * 32 + lane];
            uint2 v1 = h16[j1 * 32 + lane];
            uint2 v2 = h16[j2 * 32 + lane];
            uint2 v3 = h16[j3 * 32 + lane];
            // fp16 accumulation within the 4-group (HADD2 x8), flush to fp32
            __half2 hlo = __hadd2(__hadd2(*(__half2*)&v0.x, *(__half2*)&v1.x),
                                  __hadd2(*(__half2*)&v2.x, *(__half2*)&v3.x));
            __half2 hhi = __hadd2(__hadd2(*(__half2*)&v0.y, *(__half2*)&v1.y),
                                  __hadd2(*(__half2*)&v2.y, *(__half2*)&v3.y));
            float2 flo = __half22float2(hlo);
            float2 fhi = __half22float2(hhi);
            a0 += flo.x; a1 += flo.y; a2 += fhi.x; a3 += fhi.y;
        }
        for (; u < cnt; u++) {
            int jj = __shfl_sync(0xffffffffu, idx, u);
            uint2 v = h16[jj * 32 + lane];
            float2 f;
            f = __half22float2(*(__half2*)&v.x); a0 += f.x; a1 += f.y;
            f = __half22float2(*(__half2*)&v.y); a2 += f.x; a3 += f.y;
        }
    }
    (void)hz;
    g_s16[node * 32 + lane] = make_uint2(packh2(a0, a1), packh2(a2, a3));
}

// ---------------- fused MLP, fp16 single-term HMMA (round-5 proven) -----------------
__global__ void __launch_bounds__(256, 2) k_mlp(const float* __restrict__ b1,
                                                const float* __restrict__ b2, int l) {
    extern __shared__ char sm[];
    uint4* As = (uint4*)sm;
    uint2* Bs1 = (uint2*)(sm + 32768);
    uint2* Bs2 = (uint2*)(sm + 65536);

    int tid = threadIdx.x, wid = tid >> 5, lane = tid & 31;
    int warp_m = wid >> 2, warp_n = wid & 3;
    int m0 = blockIdx.x * 128;

    {
        const uint4* src = (const uint4*)&g_wb[l * 8192];
        uint4* dst = (uint4*)Bs1;
#pragma unroll
        for (int i = 0; i < 16; i++) dst[tid + i * 256] = src[tid + i * 256];
    }

    const uint32_t* __restrict__ S32 = (const uint32_t*)g_s16;
#pragma unroll
    for (int i = 0; i < 8; i++) {
        int s = tid + i * 256;
        int mt = s >> 8, ks = (s >> 5) & 7, ln = s & 31;
        int r = m0 + mt * 16 + (ln >> 2);
        int cp = ks * 8 + (ln & 3);
        uint4 a = make_uint4(0u, 0u, 0u, 0u);
        if (r < NN)     { a.x = S32[r * 64 + cp];       a.z = S32[r * 64 + cp + 4]; }
        if (r + 8 < NN) { a.y = S32[(r + 8) * 64 + cp]; a.w = S32[(r + 8) * 64 + cp + 4]; }
        As[s] = a;
    }
    __syncthreads();

    float d[4][4][4];
#pragma unroll
    for (int mt = 0; mt < 4; mt++)
#pragma unroll
        for (int nt = 0; nt < 4; nt++)
#pragma unroll
            for (int q = 0; q < 4; q++) d[mt][nt][q] = 0.f;

    // ---- GEMM1 ----
#pragma unroll 1
    for (int ks = 0; ks < 8; ks++) {
        uint4 ah[4];
#pragma unroll
        for (int mt = 0; mt < 4; mt++)
            ah[mt] = As[((warp_m * 4 + mt) * 8 + ks) * 32 + lane];
#pragma unroll
        for (int nt = 0; nt < 4; nt++) {
            uint2 bh = Bs1[((warp_n * 4 + nt) * 8 + ks) * 32 + lane];
#pragma unroll
            for (int mt = 0; mt < 4; mt++) mma_f16(d[mt][nt], ah[mt], bh);
        }
    }

    // ---- epilogue1 -> GEMM2 A-fragments (in-register) ----
    uint4 tf[4][2];
    {
        float aa[8], cc[8], bb[8];
#pragma unroll
        for (int j = 0; j < 8; j++) {
            int c = warp_n * 32 + (j >> 1) * 8 + (lane & 3) * 2 + (j & 1);
            bb[j] = b1[c];
            aa[j] = g_a1[l * HH + c];
            cc[j] = g_c1[l * HH + c];
        }
#pragma unroll
        for (int mt = 0; mt < 4; mt++) {
#pragma unroll
            for (int nt = 0; nt < 4; nt++) {
#pragma unroll
                for (int q = 0; q < 4; q++) {
                    float v = d[mt][nt][q] + bb[nt * 2 + (q & 1)];
                    v = v > 0.f ? v : SLOPE * v;
                    d[mt][nt][q] = aa[nt * 2 + (q & 1)] * v + cc[nt * 2 + (q & 1)];
                }
            }
#pragma unroll
            for (int kp = 0; kp < 2; kp++) {
                tf[mt][kp].x = packh2(d[mt][2 * kp][0],     d[mt][2 * kp][1]);
                tf[mt][kp].y = packh2(d[mt][2 * kp][2],     d[mt][2 * kp][3]);
                tf[mt][kp].z = packh2(d[mt][2 * kp + 1][0], d[mt][2 * kp + 1][1]);
                tf[mt][kp].w = packh2(d[mt][2 * kp + 1][2], d[mt][2 * kp + 1][3]);
            }
        }
    }
    __syncthreads();
#pragma unroll
    for (int mt = 0; mt < 4; mt++)
#pragma unroll
        for (int kp = 0; kp < 2; kp++)
            As[((warp_m * 4 + mt) * 8 + warp_n * 2 + kp) * 32 + lane] = tf[mt][kp];
    __syncthreads();

#pragma unroll
    for (int mt = 0; mt < 4; mt++)
#pragma unroll
        for (int nt = 0; nt < 4; nt++)
#pragma unroll
            for (int q = 0; q < 4; q++) d[mt][nt][q] = 0.f;

    // ---- GEMM2 ----
#pragma unroll 1
    for (int ks = 0; ks < 8; ks++) {
        uint4 ah[4];
#pragma unroll
        for (int mt = 0; mt < 4; mt++)
            ah[mt] = As[((warp_m * 4 + mt) * 8 + ks) * 32 + lane];
#pragma unroll
        for (int nt = 0; nt < 4; nt++) {
            uint2 bh = Bs2[((warp_n * 4 + nt) * 8 + ks) * 32 + lane];
#pragma unroll
            for (int mt = 0; mt < 4; mt++) mma_f16(d[mt][nt], ah[mt], bh);
        }
    }

    // ---- epilogue2: bias + leaky -> g_h16 ----
    uint32_t* __restrict__ H32 = (uint32_t*)g_h16;
#pragma unroll
    for (int nt = 0; nt < 4; nt++) {
        int c0 = warp_n * 32 + nt * 8 + (lane & 3) * 2;
        float bb0 = b2[c0], bb1 = b2[c0 + 1];
#pragma unroll
        for (int mt = 0; mt < 4; mt++) {
            int r = m0 + warp_m * 64 + mt * 16 + (lane >> 2);
            float v0 = d[mt][nt][0] + bb0, v1 = d[mt][nt][1] + bb1;
            float v2 = d[mt][nt][2] + bb0, v3 = d[mt][nt][3] + bb1;
            v0 = v0 > 0.f ? v0 : SLOPE * v0;
            v1 = v1 > 0.f ? v1 : SLOPE * v1;
            v2 = v2 > 0.f ? v2 : SLOPE * v2;
            v3 = v3 > 0.f ? v3 : SLOPE * v3;
            if (r < NN)     H32[r * 64 + c0 / 2]       = packh2(v0, v1);
            if (r + 8 < NN) H32[(r + 8) * 64 + c0 / 2] = packh2(v2, v3);
        }
    }
}

// ---------------- pooling + pooled-BN + FC (4 graphs per 256-thread block) ---------
__global__ void __launch_bounds__(256) k_pool(const float* __restrict__ fcW,
                                              const float* __restrict__ fcb,
                                              float* __restrict__ out) {
    int grp = threadIdx.x >> 6;          // 0..3
    int t = threadIdx.x & 63;            // col pair 2t,2t+1
    int g = blockIdx.x * 4 + grp;
    int beg = g_gst[g], end = g_gst[g + 1];
    const uint32_t* __restrict__ H32 = (const uint32_t*)g_h16;
    float a0 = 0.f, a1 = 0.f;
    int i = beg;
    for (; i + 4 <= end; i += 4) {
        uint32_t w0 = H32[i * 64 + t];
        uint32_t w1 = H32[(i + 1) * 64 + t];
        uint32_t w2 = H32[(i + 2) * 64 + t];
        uint32_t w3 = H32[(i + 3) * 64 + t];
        float2 f0 = __half22float2(*(__half2*)&w0);
        float2 f1 = __half22float2(*(__half2*)&w1);
        float2 f2 = __half22float2(*(__half2*)&w2);
        float2 f3 = __half22float2(*(__half2*)&w3);
        a0 += (f0.x + f1.x) + (f2.x + f3.x);
        a1 += (f0.y + f1.y) + (f2.y + f3.y);
    }
    for (; i < end; i++) {
        uint32_t v = H32[i * 64 + t];
        float2 f = __half22float2(*(__half2*)&v);
        a0 += f.x; a1 += f.y;
    }
    __shared__ float p[4][128];
    p[grp][2 * t]     = g_ap[2 * t] * a0 + g_cp[2 * t];
    p[grp][2 * t + 1] = g_ap[2 * t + 1] * a1 + g_cp[2 * t + 1];
    __syncthreads();
    float o = fcb[t];
#pragma unroll 4
    for (int k = 0; k < HH; k++) o += p[grp][k] * fcW[k * LAT + t];
    out[g * LAT + t] = o;
}

// ---------------- launcher ----------------
extern "C" void kernel_launch(void* const* d_in, const int* in_sizes, int n_in,
                              void* d_out, int out_size) {
    const float* x     = (const float*)d_in[0];
    const int*   ei    = (const int*)d_in[1];
    const int*   batch = (const int*)d_in[2];
    const float* W1    = (const float*)d_in[3];
    const float* b1    = (const float*)d_in[4];
    const float* g1    = (const float*)d_in[5];
    const float* beta1 = (const float*)d_in[6];
    const float* rm1   = (const float*)d_in[7];
    const float* rv1   = (const float*)d_in[8];
    const float* W2    = (const float*)d_in[9];
    const float* b2    = (const float*)d_in[10];
    const float* bng   = (const float*)d_in[11];
    const float* bnb   = (const float*)d_in[12];
    const float* bnrm  = (const float*)d_in[13];
    const float* bnrv  = (const float*)d_in[14];
    const float* fcW   = (const float*)d_in[15];
    const float* fcb   = (const float*)d_in[16];
    float* out = (float*)d_out;
    const int* src = ei;
    const int* dst = ei + EE;

    const int smem = 98304;
    cudaFuncSetAttribute(k_mlp, cudaFuncAttributeMaxDynamicSharedMemorySize, smem);

    k_setup<<<9458, 256>>>(x, batch, dst, g1, beta1, rm1, rv1,
                           bng, bnb, bnrm, bnrv, W1, W2);
    k_scan<<<NB_SCAN, 1024>>>();
    k_scatter<<<(EE + 255) / 256, 256>>>(src, dst);

    const int gb = (NN + 127) / 128;   // 782
    for (int l = 0; l < LL; l++) {
        k_agg<<<(NN + 7) / 8, 256>>>(l);
        k_mlp<<<gb, 256, smem>>>(b1 + l * HH, b2 + l * HH, l);
    }
    k_pool<<<(GG + 3) / 4, 256>>>(fcW, fcb, out);
}